// round 14
// baseline (speedup 1.0000x reference)
#include <cuda_runtime.h>
#include <cuda_fp16.h>
#include <cstdint>

#define NB 2
#define NN 30000
#define NE 120000
#define KF 512
#define NH 4
#define DH 128
#define OF 512
#define NBH 8
#define NBLK 235
#define LN_EPS 1e-5f

__device__ __half g_t[(size_t)NN * NB * OF];   // [n][b][512] fp16
__device__ __half g_wthi[OF * KF];             // [col][k], col = h*128+d
__device__ float  g_ssrc[(size_t)NN * NBH];    // [n][b*4+h]
__device__ float  g_sdst[(size_t)NN * NBH];
__device__ float  g_sc[(size_t)NE * NBH];      // [e][b*4+h]
__device__ float  g_sum[NBH];
__device__ int    g_cnt[NN];
__device__ int    g_bsum[NBLK];
__device__ int    g_boff[NBLK];
__device__ int    g_off[NN + 1];
__device__ int    g_cur[NN];
__device__ int    g_eid[NE];
__device__ int    g_is64;

__device__ __forceinline__ int esrc(const void* ep, int e, int is64) {
    return is64 ? (int)((const long long*)ep)[e] : ((const int*)ep)[e];
}
__device__ __forceinline__ int edst(const void* ep, int e, int is64) {
    return is64 ? (int)((const long long*)ep)[NE + e] : ((const int*)ep)[NE + e];
}
__device__ __forceinline__ uint32_t smem_u32(const void* p) {
    uint32_t a;
    asm("{ .reg .u64 t; cvta.to.shared.u64 t, %1; cvt.u32.u64 %0, t; }" : "=r"(a) : "l"(p));
    return a;
}
__device__ __forceinline__ void cpa16(uint32_t dst, const void* src) {
    asm volatile("cp.async.ca.shared.global [%0], [%1], 16;"
                 :: "r"(dst), "l"(src) : "memory");
}
__device__ __forceinline__ void ldsm_x4(uint32_t addr, uint32_t& r0, uint32_t& r1,
                                        uint32_t& r2, uint32_t& r3) {
    asm volatile("ldmatrix.sync.aligned.m8n8.x4.shared.b16 {%0,%1,%2,%3}, [%4];"
                 : "=r"(r0), "=r"(r1), "=r"(r2), "=r"(r3) : "r"(addr));
}

// ---------------- prep kernels ----------------
__global__ void k_detect(const int* ei32) {
    if (threadIdx.x == 0) {
        int ok = 1;
        for (int j = 0; j < 64; j++)
            if (ei32[2 * j + 1] != 0) ok = 0;
        g_is64 = ok;
    }
}
__global__ void k_init() {
    int i = blockIdx.x * blockDim.x + threadIdx.x;
    if (i < NN) g_cnt[i] = 0;
    if (i < NBH) g_sum[i] = 0.f;
}
__global__ void k_convw(const float* __restrict__ W) {
    int i = blockIdx.x * blockDim.x + threadIdx.x;  // h,k,d
    if (i >= NH * KF * DH) return;
    int h = i / (KF * DH), r = i % (KF * DH), k = r / DH, d = r % DH;
    int n = h * DH + d;
    g_wthi[(size_t)n * KF + k] = __float2half_rn(W[i]);
}

// ---------------- mma.sync GEMM: 128x128 per CTA, K=512, 2-term fp16 -------
#define PITCHB 80
#define TERMB  10240
#define BUFB   30720
#define SMEMB  61440

__device__ __forceinline__ void ldgA(float4* ar, const float* __restrict__ xb,
                                     int m0, int kc, int tid) {
    #pragma unroll
    for (int j = 0; j < 4; j++) {
        int idx = j * 256 + tid;
        int row = idx >> 3, c4 = idx & 7;
        int gr = m0 + row;
        ar[j] = (gr < NN) ? *(const float4*)(xb + (size_t)gr * KF + kc * 32 + c4 * 4)
                          : make_float4(0.f, 0.f, 0.f, 0.f);
    }
}
__device__ __forceinline__ void stsA(const float4* ar, char* sm, int buf, int tid) {
    char* base = sm + buf * BUFB;
    #pragma unroll
    for (int j = 0; j < 4; j++) {
        int idx = j * 256 + tid;
        int row = idx >> 3, c4 = idx & 7;
        float4 v = ar[j];
        __half h0 = __float2half_rn(v.x), h1 = __float2half_rn(v.y);
        __half h2 = __float2half_rn(v.z), h3 = __float2half_rn(v.w);
        uint32_t hi0 = (uint32_t)__half_as_ushort(h0) |
                       ((uint32_t)__half_as_ushort(h1) << 16);
        uint32_t hi1 = (uint32_t)__half_as_ushort(h2) |
                       ((uint32_t)__half_as_ushort(h3) << 16);
        __half l0 = __float2half_rn(v.x - __half2float(h0));
        __half l1 = __float2half_rn(v.y - __half2float(h1));
        __half l2 = __float2half_rn(v.z - __half2float(h2));
        __half l3 = __float2half_rn(v.w - __half2float(h3));
        uint32_t lo0 = (uint32_t)__half_as_ushort(l0) |
                       ((uint32_t)__half_as_ushort(l1) << 16);
        uint32_t lo1 = (uint32_t)__half_as_ushort(l2) |
                       ((uint32_t)__half_as_ushort(l3) << 16);
        char* p = base + row * PITCHB + c4 * 8;
        *(uint2*)p = make_uint2(hi0, hi1);
        *(uint2*)(p + TERMB) = make_uint2(lo0, lo1);
    }
}
__device__ __forceinline__ void loadB(uint32_t sb, int buf, int kc, int bn, int tid) {
    #pragma unroll
    for (int i = 0; i < 2; i++) {
        int idx = i * 256 + tid;
        int row = idx >> 2, seg = idx & 3;
        uint32_t dst = sb + buf * BUFB + 2 * TERMB + row * PITCHB + seg * 16;
        const __half* src = g_wthi + (size_t)(bn + row) * KF + kc * 32 + seg * 8;
        cpa16(dst, src);
    }
    asm volatile("cp.async.commit_group;" ::: "memory");
}

#define MMA_F16(c, a0, a1, a2, a3, b0, b1) \
    asm volatile( \
        "mma.sync.aligned.m16n8k16.row.col.f32.f16.f16.f32 " \
        "{%0,%1,%2,%3}, {%4,%5,%6,%7}, {%8,%9}, {%0,%1,%2,%3};" \
        : "+f"((c)[0]), "+f"((c)[1]), "+f"((c)[2]), "+f"((c)[3]) \
        : "r"(a0), "r"(a1), "r"(a2), "r"(a3), "r"(b0), "r"(b1))

__global__ __launch_bounds__(256, 2) void k_gemm_mma(const float* __restrict__ x,
                                                     const float* __restrict__ ga,
                                                     int b) {
    extern __shared__ float4 smf4[];
    char* sm = (char*)smf4;
    uint32_t sb = smem_u32(sm);
    int tid = threadIdx.x, lid = tid & 31, wid = tid >> 5;
    int gid = lid >> 2, tig = lid & 3;
    int wM = wid & 3, wN = wid >> 2;
    int hx = blockIdx.x;
    int m0 = blockIdx.y * 128, bn = hx * 128;
    const float* xb = x + (size_t)b * NN * KF;

    uint32_t aoff = (uint32_t)((lid & 15) * PITCHB + (((lid >> 4) << 3)) * 2);
    uint32_t boff = (uint32_t)((((lid & 7) + ((lid >> 4) << 3))) * PITCHB +
                               ((((lid >> 3) & 1) << 3)) * 2);

    float acc[2][8][4];
    #pragma unroll
    for (int mi = 0; mi < 2; mi++)
        #pragma unroll
        for (int ni = 0; ni < 8; ni++)
            #pragma unroll
            for (int q = 0; q < 4; q++) acc[mi][ni][q] = 0.f;

    float4 ar[4];
    ldgA(ar, xb, m0, 0, tid);
    stsA(ar, sm, 0, tid);
    loadB(sb, 0, 0, bn, tid);
    ldgA(ar, xb, m0, 1, tid);

    for (int kc = 0; kc < 16; kc++) {
        if (kc < 15) {
            stsA(ar, sm, (kc + 1) & 1, tid);
            loadB(sb, (kc + 1) & 1, kc + 1, bn, tid);
            if (kc < 14) ldgA(ar, xb, m0, kc + 2, tid);
            asm volatile("cp.async.wait_group 1;" ::: "memory");
        } else {
            asm volatile("cp.async.wait_group 0;" ::: "memory");
        }
        __syncthreads();
        uint32_t sA = sb + (kc & 1) * BUFB;
        uint32_t sB = sA + 2 * TERMB;
        #pragma unroll
        for (int s = 0; s < 2; s++) {
            uint32_t Abase = sA + wM * 32 * PITCHB + aoff + s * 32;
            uint32_t Bbase = sB + wN * 64 * PITCHB + boff + s * 32;
            uint32_t ah[2][4];
            ldsm_x4(Abase,                ah[0][0], ah[0][1], ah[0][2], ah[0][3]);
            ldsm_x4(Abase + 16 * PITCHB,  ah[1][0], ah[1][1], ah[1][2], ah[1][3]);
            uint32_t al[2][4];
            ldsm_x4(Abase + TERMB,               al[0][0], al[0][1], al[0][2], al[0][3]);
            ldsm_x4(Abase + TERMB + 16 * PITCHB, al[1][0], al[1][1], al[1][2], al[1][3]);
            uint32_t bh_[8][2];
            #pragma unroll
            for (int j = 0; j < 4; j++)
                ldsm_x4(Bbase + j * 16 * PITCHB,
                        bh_[2 * j][0], bh_[2 * j][1], bh_[2 * j + 1][0], bh_[2 * j + 1][1]);
            #pragma unroll
            for (int ni = 0; ni < 8; ni++) {
                MMA_F16(acc[0][ni], ah[0][0], ah[0][1], ah[0][2], ah[0][3], bh_[ni][0], bh_[ni][1]);
                MMA_F16(acc[1][ni], ah[1][0], ah[1][1], ah[1][2], ah[1][3], bh_[ni][0], bh_[ni][1]);
            }
            #pragma unroll
            for (int ni = 0; ni < 8; ni++) {
                MMA_F16(acc[0][ni], al[0][0], al[0][1], al[0][2], al[0][3], bh_[ni][0], bh_[ni][1]);
                MMA_F16(acc[1][ni], al[1][0], al[1][1], al[1][2], al[1][3], bh_[ni][0], bh_[ni][1]);
            }
        }
        __syncthreads();
    }

    // epilogue: write g_t[n][b][512] (fp16) + fused s_src/s_dst dots for head hx
    float psrc[2][2] = {{0.f, 0.f}, {0.f, 0.f}};
    float pdst[2][2] = {{0.f, 0.f}, {0.f, 0.f}};
    #pragma unroll
    for (int mi = 0; mi < 2; mi++) {
        #pragma unroll
        for (int ni = 0; ni < 8; ni++) {
            int row = m0 + wM * 32 + mi * 16 + gid;
            int d0 = wN * 64 + ni * 8 + tig * 2;
            float c0 = acc[mi][ni][0], c1 = acc[mi][ni][1];
            float c2 = acc[mi][ni][2], c3 = acc[mi][ni][3];
            float a0 = __ldg(ga + hx * 256 + d0);
            float a1 = __ldg(ga + hx * 256 + d0 + 1);
            float e0 = __ldg(ga + hx * 256 + 128 + d0);
            float e1 = __ldg(ga + hx * 256 + 128 + d0 + 1);
            psrc[mi][0] += c0 * a0 + c1 * a1;
            psrc[mi][1] += c2 * a0 + c3 * a1;
            pdst[mi][0] += c0 * e0 + c1 * e1;
            pdst[mi][1] += c2 * e0 + c3 * e1;
            __half* base = g_t + ((size_t)row * NB + b) * OF + hx * 128 + d0;
            if (row < NN) *(__half2*)base = __floats2half2_rn(c0, c1);
            if (row + 8 < NN)
                *(__half2*)(base + 8 * (size_t)(NB * OF)) = __floats2half2_rn(c2, c3);
        }
    }
    #pragma unroll
    for (int mi = 0; mi < 2; mi++)
        #pragma unroll
        for (int hf = 0; hf < 2; hf++) {
            float v = psrc[mi][hf];
            v += __shfl_xor_sync(0xffffffffu, v, 1);
            v += __shfl_xor_sync(0xffffffffu, v, 2);
            psrc[mi][hf] = v;
            float w = pdst[mi][hf];
            w += __shfl_xor_sync(0xffffffffu, w, 1);
            w += __shfl_xor_sync(0xffffffffu, w, 2);
            pdst[mi][hf] = w;
        }
    float* sred = (float*)sm;
    if (tig == 0) {
        #pragma unroll
        for (int mi = 0; mi < 2; mi++) {
            int r0 = wM * 32 + mi * 16 + gid;
            sred[(wN * 128 + r0) * 2]         = psrc[mi][0];
            sred[(wN * 128 + r0) * 2 + 1]     = pdst[mi][0];
            sred[(wN * 128 + r0 + 8) * 2]     = psrc[mi][1];
            sred[(wN * 128 + r0 + 8) * 2 + 1] = pdst[mi][1];
        }
    }
    __syncthreads();
    if (tid < 128) {
        int n = m0 + tid;
        if (n < NN) {
            float ss = sred[tid * 2] + sred[(128 + tid) * 2];
            float sd = sred[tid * 2 + 1] + sred[(128 + tid) * 2 + 1];
            g_ssrc[(size_t)n * NBH + b * 4 + hx] = ss;
            g_sdst[(size_t)n * NBH + b * 4 + hx] = sd;
        }
    }
}

// ---------------- per-batch edge softmax (no max pass) ----------------
__global__ __launch_bounds__(256) void k_sm(const void* ep, int b) {
    __shared__ float wred[8][4];
    int tid = threadIdx.x, wid = tid >> 5, lid = tid & 31;
    int is64 = g_is64;
    int e = blockIdx.x * 256 + tid;
    float pv[4];
    if (e < NE) {
        int sn = esrc(ep, e, is64), dn = edst(ep, e, is64);
        const float* ps = g_ssrc + (size_t)sn * NBH + b * 4;
        const float* pd = g_sdst + (size_t)dn * NBH + b * 4;
        #pragma unroll
        for (int i = 0; i < 4; i++) {
            float s = ps[i] + pd[i];
            s = (s > 0.f) ? s : 0.2f * s;
            float p = __expf(s);
            pv[i] = p;
            g_sc[(size_t)e * NBH + b * 4 + i] = p;
        }
    } else {
        #pragma unroll
        for (int i = 0; i < 4; i++) pv[i] = 0.f;
    }
    #pragma unroll
    for (int i = 0; i < 4; i++) {
        float s = pv[i];
        #pragma unroll
        for (int o = 16; o > 0; o >>= 1) s += __shfl_xor_sync(0xffffffffu, s, o);
        if (lid == 0) wred[wid][i] = s;
    }
    __syncthreads();
    if (tid < 4) {
        float s = 0.f;
        #pragma unroll
        for (int w = 0; w < 8; w++) s += wred[w][tid];
        atomicAdd(&g_sum[b * 4 + tid], s);
    }
}

// ---------------- CSR build (parallel deterministic scan) ----------------
__global__ void k_count(const void* ep) {
    int e = blockIdx.x * 256 + threadIdx.x;
    if (e < NE) atomicAdd(&g_cnt[edst(ep, e, g_is64)], 1);
}
__global__ __launch_bounds__(128) void k_bsum() {
    __shared__ int ws[4];
    int tid = threadIdx.x;
    int i = blockIdx.x * 128 + tid;
    int c = (i < NN) ? g_cnt[i] : 0;
    int v = c;
    #pragma unroll
    for (int o = 16; o > 0; o >>= 1) v += __shfl_down_sync(0xffffffffu, v, o);
    if ((tid & 31) == 0) ws[tid >> 5] = v;
    __syncthreads();
    if (tid == 0) g_bsum[blockIdx.x] = ws[0] + ws[1] + ws[2] + ws[3];
}
__global__ __launch_bounds__(256) void k_bscan() {
    __shared__ int s[256];
    int t = threadIdx.x;
    int v = (t < NBLK) ? g_bsum[t] : 0;
    s[t] = v;
    __syncthreads();
    for (int o = 1; o < 256; o <<= 1) {
        int u = (t >= o) ? s[t - o] : 0;
        __syncthreads();
        s[t] += u;
        __syncthreads();
    }
    if (t < NBLK) g_boff[t] = s[t] - v;
    if (t == NBLK - 1) g_off[NN] = s[t];
}
__global__ __launch_bounds__(128) void k_off() {
    __shared__ int ws[4];
    int tid = threadIdx.x, lane = tid & 31, warp = tid >> 5;
    int i = blockIdx.x * 128 + tid;
    int c = (i < NN) ? g_cnt[i] : 0;
    int v = c;
    #pragma unroll
    for (int o = 1; o < 32; o <<= 1) {
        int u = __shfl_up_sync(0xffffffffu, v, o);
        if (lane >= o) v += u;
    }
    if (lane == 31) ws[warp] = v;
    __syncthreads();
    int add = 0;
    #pragma unroll
    for (int w = 0; w < 4; w++) add += (w < warp) ? ws[w] : 0;
    int excl = v - c + add + g_boff[blockIdx.x];
    if (i < NN) { g_off[i] = excl; g_cur[i] = excl; }
}
__global__ void k_fill(const void* ep) {
    int e = blockIdx.x * 256 + threadIdx.x;
    if (e < NE) {
        int pos = atomicAdd(&g_cur[edst(ep, e, g_is64)], 1);
        g_eid[pos] = e;
    }
}

// ---------------- per-batch aggregate + layernorm ----------------
// Thread tid owns half2 pairs s=0,1 within the (n,b) row; head = 2s + (tid>>6).
__global__ __launch_bounds__(128) void k_agg(const void* ep,
                                             const float* __restrict__ gamma,
                                             const float* __restrict__ beta,
                                             float* __restrict__ out, int b) {
    __shared__ float red[8];
    __shared__ int   s_sn[32];
    __shared__ float s_w[32][4];
    int is64 = g_is64;
    int n = blockIdx.x;
    int tid = threadIdx.x;
    int hsel = tid >> 6;
    float2 acc[2] = {};
    int e0 = g_off[n], e1 = g_off[n + 1];
    for (int base = e0; base < e1; base += 32) {
        int cnt = min(32, e1 - base);
        __syncthreads();
        if (tid < cnt) {
            int e = g_eid[base + tid];
            s_sn[tid] = esrc(ep, e, is64);
            *(float4*)&s_w[tid][0] = *(const float4*)(g_sc + (size_t)e * NBH + b * 4);
        }
        __syncthreads();
        for (int j = 0; j < cnt; j++) {
            const __half2* trow =
                (const __half2*)(g_t + ((size_t)s_sn[j] * NB + b) * OF);
            #pragma unroll
            for (int s = 0; s < 2; s++) {
                float2 f = __half22float2(trow[s * 128 + tid]);
                float w = s_w[j][2 * s + hsel];
                acc[s].x += w * f.x;
                acc[s].y += w * f.y;
            }
        }
    }
    __syncthreads();
    #pragma unroll
    for (int s = 0; s < 2; s++) {
        float inv = 1.f / g_sum[b * 4 + 2 * s + hsel];
        acc[s].x *= inv;
        acc[s].y *= inv;
    }
    float s1 = acc[0].x + acc[0].y + acc[1].x + acc[1].y;
    float s2 = acc[0].x * acc[0].x + acc[0].y * acc[0].y +
               acc[1].x * acc[1].x + acc[1].y * acc[1].y;
    #pragma unroll
    for (int o = 16; o > 0; o >>= 1) {
        s1 += __shfl_down_sync(0xffffffffu, s1, o);
        s2 += __shfl_down_sync(0xffffffffu, s2, o);
    }
    if ((tid & 31) == 0) { red[(tid >> 5) * 2] = s1; red[(tid >> 5) * 2 + 1] = s2; }
    __syncthreads();
    float t1 = red[0] + red[2] + red[4] + red[6];
    float t2 = red[1] + red[3] + red[5] + red[7];
    float mu = t1 / (float)OF;
    float var = t2 / (float)OF - mu * mu;
    float rs = rsqrtf(var + LN_EPS);
    float* op = out + ((size_t)b * NN + n) * OF;
    #pragma unroll
    for (int s = 0; s < 2; s++) {
        int jj = s * 256 + 2 * tid;
        float2 v = acc[s];
        float2 o;
        o.x = (v.x - mu) * rs * gamma[jj] + beta[jj];
        o.y = (v.y - mu) * rs * gamma[jj + 1] + beta[jj + 1];
        *(float2*)(op + jj) = o;
    }
}

extern "C" void kernel_launch(void* const* d_in, const int* in_sizes, int n_in,
                              void* d_out, int out_size) {
    const float* x     = (const float*)d_in[0];
    const void*  ei    = d_in[1];
    const float* W     = (const float*)d_in[2];
    const float* a     = (const float*)d_in[3];
    const float* gamma = (const float*)d_in[4];
    const float* beta  = (const float*)d_in[5];
    float* out = (float*)d_out;

    static cudaStream_t s1 = nullptr, s2 = nullptr;
    static cudaEvent_t ev0 = nullptr, ev1 = nullptr, evG0 = nullptr, ev2 = nullptr;
    if (!s1) {
        cudaStreamCreateWithFlags(&s1, cudaStreamNonBlocking);
        cudaStreamCreateWithFlags(&s2, cudaStreamNonBlocking);
        cudaEventCreateWithFlags(&ev0, cudaEventDisableTiming);
        cudaEventCreateWithFlags(&ev1, cudaEventDisableTiming);
        cudaEventCreateWithFlags(&evG0, cudaEventDisableTiming);
        cudaEventCreateWithFlags(&ev2, cudaEventDisableTiming);
        cudaFuncSetAttribute(k_gemm_mma, cudaFuncAttributeMaxDynamicSharedMemorySize, SMEMB);
    }

    k_convw<<<(NH * KF * DH + 255) / 256, 256>>>(W);

    // fork s1: CSR build (depends only on edges)
    cudaEventRecord(ev0, 0);
    cudaStreamWaitEvent(s1, ev0, 0);
    k_detect<<<1, 32, 0, s1>>>((const int*)ei);
    k_init<<<(NN + 255) / 256, 256, 0, s1>>>();
    k_count<<<(NE + 255) / 256, 256, 0, s1>>>(ei);
    k_bsum<<<NBLK, 128, 0, s1>>>();
    k_bscan<<<1, 256, 0, s1>>>();
    k_off<<<NBLK, 128, 0, s1>>>();
    k_fill<<<(NE + 255) / 256, 256, 0, s1>>>(ei);
    cudaEventRecord(ev1, s1);

    dim3 gg(OF / 128, (NN + 127) / 128, 1);
    // GEMM batch 0 on main
    k_gemm_mma<<<gg, 256, SMEMB>>>(x, a, 0);
    cudaEventRecord(evG0, 0);

    // s2: batch-0 tail, concurrent with GEMM batch 1
    cudaStreamWaitEvent(s2, evG0, 0);
    cudaStreamWaitEvent(s2, ev1, 0);
    k_sm<<<(NE + 255) / 256, 256, 0, s2>>>(ei, 0);
    k_agg<<<NN, 128, 0, s2>>>(ei, gamma, beta, out, 0);
    cudaEventRecord(ev2, s2);

    // GEMM batch 1 + batch-1 tail on main
    k_gemm_mma<<<gg, 256, SMEMB>>>(x, a, 1);
    cudaStreamWaitEvent(0, ev1, 0);
    k_sm<<<(NE + 255) / 256, 256>>>(ei, 1);
    k_agg<<<NN, 128>>>(ei, gamma, beta, out, 1);

    // join batch-0 tail
    cudaStreamWaitEvent(0, ev2, 0);
}

// round 15
// speedup vs baseline: 1.1209x; 1.1209x over previous
#include <cuda_runtime.h>
#include <cuda_fp16.h>
#include <cstdint>

#define NB 2
#define NN 30000
#define NE 120000
#define KF 512
#define NH 4
#define DH 128
#define OF 512
#define NBH 8
#define NBLK 235
#define LN_EPS 1e-5f

__device__ __half g_t[(size_t)NN * NB * OF];   // [n][b][512] fp16
__device__ __half g_wthi[OF * KF];             // [col][k], col = h*128+d
__device__ float  g_ssrc[(size_t)NN * NBH];    // [n][b*4+h]
__device__ float  g_sdst[(size_t)NN * NBH];
__device__ float  g_sc[(size_t)NE * NBH];      // [e][b*4+h]
__device__ float  g_sum[NBH];
__device__ int    g_cnt[NN];
__device__ int    g_bsum[NBLK];
__device__ int    g_boff[NBLK];
__device__ int    g_off[NN + 1];
__device__ int    g_cur[NN];
__device__ int    g_eid[NE];
__device__ int    g_is64;

__device__ __forceinline__ int esrc(const void* ep, int e, int is64) {
    return is64 ? (int)((const long long*)ep)[e] : ((const int*)ep)[e];
}
__device__ __forceinline__ int edst(const void* ep, int e, int is64) {
    return is64 ? (int)((const long long*)ep)[NE + e] : ((const int*)ep)[NE + e];
}
__device__ __forceinline__ uint32_t smem_u32(const void* p) {
    uint32_t a;
    asm("{ .reg .u64 t; cvta.to.shared.u64 t, %1; cvt.u32.u64 %0, t; }" : "=r"(a) : "l"(p));
    return a;
}
__device__ __forceinline__ void cpa16(uint32_t dst, const void* src) {
    asm volatile("cp.async.ca.shared.global [%0], [%1], 16;"
                 :: "r"(dst), "l"(src) : "memory");
}
__device__ __forceinline__ void ldsm_x4(uint32_t addr, uint32_t& r0, uint32_t& r1,
                                        uint32_t& r2, uint32_t& r3) {
    asm volatile("ldmatrix.sync.aligned.m8n8.x4.shared.b16 {%0,%1,%2,%3}, [%4];"
                 : "=r"(r0), "=r"(r1), "=r"(r2), "=r"(r3) : "r"(addr));
}

// ---------------- prep kernels ----------------
__global__ void k_detect(const int* ei32) {
    if (threadIdx.x == 0) {
        int ok = 1;
        for (int j = 0; j < 64; j++)
            if (ei32[2 * j + 1] != 0) ok = 0;
        g_is64 = ok;
    }
}
__global__ void k_init() {
    int i = blockIdx.x * blockDim.x + threadIdx.x;
    if (i < NN) g_cnt[i] = 0;
    if (i < NBH) g_sum[i] = 0.f;
}
__global__ void k_convw(const float* __restrict__ W) {
    int i = blockIdx.x * blockDim.x + threadIdx.x;  // h,k,d
    if (i >= NH * KF * DH) return;
    int h = i / (KF * DH), r = i % (KF * DH), k = r / DH, d = r % DH;
    int n = h * DH + d;
    g_wthi[(size_t)n * KF + k] = __float2half_rn(W[i]);
}

// ---- mma.sync GEMM: 128x128/CTA, K=512, 2-term fp16, 3-stage pipeline ----
// SMEM: A bufs 0..2 at buf*20480 (hi +0, lo +10240); B bufs 0..2 at 61440+buf*10240.
#define PITCHB 80
#define TERMB  10240
#define ABUFB  20480
#define BBASE  61440
#define SMEMB  92160

__device__ __forceinline__ void ldgA(float4* ar, const float* __restrict__ xb,
                                     int m0, int kc, int tid) {
    #pragma unroll
    for (int j = 0; j < 4; j++) {
        int idx = j * 256 + tid;
        int row = idx >> 3, c4 = idx & 7;
        int gr = m0 + row;
        ar[j] = (gr < NN) ? *(const float4*)(xb + (size_t)gr * KF + kc * 32 + c4 * 4)
                          : make_float4(0.f, 0.f, 0.f, 0.f);
    }
}
__device__ __forceinline__ void stsA(const float4* ar, char* sm, int buf, int tid) {
    char* base = sm + buf * ABUFB;
    #pragma unroll
    for (int j = 0; j < 4; j++) {
        int idx = j * 256 + tid;
        int row = idx >> 3, c4 = idx & 7;
        float4 v = ar[j];
        __half h0 = __float2half_rn(v.x), h1 = __float2half_rn(v.y);
        __half h2 = __float2half_rn(v.z), h3 = __float2half_rn(v.w);
        uint32_t hi0 = (uint32_t)__half_as_ushort(h0) |
                       ((uint32_t)__half_as_ushort(h1) << 16);
        uint32_t hi1 = (uint32_t)__half_as_ushort(h2) |
                       ((uint32_t)__half_as_ushort(h3) << 16);
        __half l0 = __float2half_rn(v.x - __half2float(h0));
        __half l1 = __float2half_rn(v.y - __half2float(h1));
        __half l2 = __float2half_rn(v.z - __half2float(h2));
        __half l3 = __float2half_rn(v.w - __half2float(h3));
        uint32_t lo0 = (uint32_t)__half_as_ushort(l0) |
                       ((uint32_t)__half_as_ushort(l1) << 16);
        uint32_t lo1 = (uint32_t)__half_as_ushort(l2) |
                       ((uint32_t)__half_as_ushort(l3) << 16);
        char* p = base + row * PITCHB + c4 * 8;
        *(uint2*)p = make_uint2(hi0, hi1);
        *(uint2*)(p + TERMB) = make_uint2(lo0, lo1);
    }
}
__device__ __forceinline__ void loadB(uint32_t sb, int buf, int kc, int bn, int tid) {
    #pragma unroll
    for (int i = 0; i < 2; i++) {
        int idx = i * 256 + tid;
        int row = idx >> 2, seg = idx & 3;
        uint32_t dst = sb + BBASE + buf * TERMB + row * PITCHB + seg * 16;
        const __half* src = g_wthi + (size_t)(bn + row) * KF + kc * 32 + seg * 8;
        cpa16(dst, src);
    }
    asm volatile("cp.async.commit_group;" ::: "memory");
}

#define MMA_F16(c, a0, a1, a2, a3, b0, b1) \
    asm volatile( \
        "mma.sync.aligned.m16n8k16.row.col.f32.f16.f16.f32 " \
        "{%0,%1,%2,%3}, {%4,%5,%6,%7}, {%8,%9}, {%0,%1,%2,%3};" \
        : "+f"((c)[0]), "+f"((c)[1]), "+f"((c)[2]), "+f"((c)[3]) \
        : "r"(a0), "r"(a1), "r"(a2), "r"(a3), "r"(b0), "r"(b1))

__global__ __launch_bounds__(256, 2) void k_gemm_mma(const float* __restrict__ x,
                                                     const float* __restrict__ ga) {
    extern __shared__ float4 smf4[];
    char* sm = (char*)smf4;
    uint32_t sb = smem_u32(sm);
    int tid = threadIdx.x, lid = tid & 31, wid = tid >> 5;
    int gid = lid >> 2, tig = lid & 3;
    int wM = wid & 3, wN = wid >> 2;
    int hx = blockIdx.x;
    int m0 = blockIdx.y * 128, bn = hx * 128;
    int b = blockIdx.z;
    const float* xb = x + (size_t)b * NN * KF;

    uint32_t aoff = (uint32_t)((lid & 15) * PITCHB + (((lid >> 4) << 3)) * 2);
    uint32_t boff = (uint32_t)((((lid & 7) + ((lid >> 4) << 3))) * PITCHB +
                               ((((lid >> 3) & 1) << 3)) * 2);

    float acc[2][8][4];
    #pragma unroll
    for (int mi = 0; mi < 2; mi++)
        #pragma unroll
        for (int ni = 0; ni < 8; ni++)
            #pragma unroll
            for (int q = 0; q < 4; q++) acc[mi][ni][q] = 0.f;

    float4 ar[4];
    ldgA(ar, xb, m0, 0, tid);
    stsA(ar, sm, 0, tid);
    ldgA(ar, xb, m0, 1, tid);
    loadB(sb, 0, 0, bn, tid);
    loadB(sb, 1, 1, bn, tid);

    for (int kc = 0; kc < 16; kc++) {
        int cb = kc % 3;
        if (kc < 15) stsA(ar, sm, (kc + 1) % 3, tid);
        if (kc < 14) ldgA(ar, xb, m0, kc + 2, tid);
        if (kc < 15) {
            asm volatile("cp.async.wait_group 1;" ::: "memory");
        } else {
            asm volatile("cp.async.wait_group 0;" ::: "memory");
        }
        __syncthreads();
        if (kc < 14) loadB(sb, (kc + 2) % 3, kc + 2, bn, tid);

        uint32_t sA = sb + cb * ABUFB;
        uint32_t sB = sb + BBASE + cb * TERMB;
        #pragma unroll
        for (int s = 0; s < 2; s++) {
            uint32_t Abase = sA + wM * 32 * PITCHB + aoff + s * 32;
            uint32_t Bbase = sB + wN * 64 * PITCHB + boff + s * 32;
            uint32_t ah[2][4];
            ldsm_x4(Abase,                ah[0][0], ah[0][1], ah[0][2], ah[0][3]);
            ldsm_x4(Abase + 16 * PITCHB,  ah[1][0], ah[1][1], ah[1][2], ah[1][3]);
            uint32_t al[2][4];
            ldsm_x4(Abase + TERMB,               al[0][0], al[0][1], al[0][2], al[0][3]);
            ldsm_x4(Abase + TERMB + 16 * PITCHB, al[1][0], al[1][1], al[1][2], al[1][3]);
            uint32_t bh_[8][2];
            #pragma unroll
            for (int j = 0; j < 4; j++)
                ldsm_x4(Bbase + j * 16 * PITCHB,
                        bh_[2 * j][0], bh_[2 * j][1], bh_[2 * j + 1][0], bh_[2 * j + 1][1]);
            #pragma unroll
            for (int ni = 0; ni < 8; ni++) {
                MMA_F16(acc[0][ni], ah[0][0], ah[0][1], ah[0][2], ah[0][3], bh_[ni][0], bh_[ni][1]);
                MMA_F16(acc[1][ni], ah[1][0], ah[1][1], ah[1][2], ah[1][3], bh_[ni][0], bh_[ni][1]);
            }
            #pragma unroll
            for (int ni = 0; ni < 8; ni++) {
                MMA_F16(acc[0][ni], al[0][0], al[0][1], al[0][2], al[0][3], bh_[ni][0], bh_[ni][1]);
                MMA_F16(acc[1][ni], al[1][0], al[1][1], al[1][2], al[1][3], bh_[ni][0], bh_[ni][1]);
            }
        }
    }

    // epilogue: write g_t[n][b][512] (fp16) + fused s_src/s_dst dots for head hx
    float psrc[2][2] = {{0.f, 0.f}, {0.f, 0.f}};
    float pdst[2][2] = {{0.f, 0.f}, {0.f, 0.f}};
    #pragma unroll
    for (int mi = 0; mi < 2; mi++) {
        #pragma unroll
        for (int ni = 0; ni < 8; ni++) {
            int row = m0 + wM * 32 + mi * 16 + gid;
            int d0 = wN * 64 + ni * 8 + tig * 2;
            float c0 = acc[mi][ni][0], c1 = acc[mi][ni][1];
            float c2 = acc[mi][ni][2], c3 = acc[mi][ni][3];
            float a0 = __ldg(ga + hx * 256 + d0);
            float a1 = __ldg(ga + hx * 256 + d0 + 1);
            float e0 = __ldg(ga + hx * 256 + 128 + d0);
            float e1 = __ldg(ga + hx * 256 + 128 + d0 + 1);
            psrc[mi][0] += c0 * a0 + c1 * a1;
            psrc[mi][1] += c2 * a0 + c3 * a1;
            pdst[mi][0] += c0 * e0 + c1 * e1;
            pdst[mi][1] += c2 * e0 + c3 * e1;
            __half* base = g_t + ((size_t)row * NB + b) * OF + hx * 128 + d0;
            if (row < NN) *(__half2*)base = __floats2half2_rn(c0, c1);
            if (row + 8 < NN)
                *(__half2*)(base + 8 * (size_t)(NB * OF)) = __floats2half2_rn(c2, c3);
        }
    }
    #pragma unroll
    for (int mi = 0; mi < 2; mi++)
        #pragma unroll
        for (int hf = 0; hf < 2; hf++) {
            float v = psrc[mi][hf];
            v += __shfl_xor_sync(0xffffffffu, v, 1);
            v += __shfl_xor_sync(0xffffffffu, v, 2);
            psrc[mi][hf] = v;
            float w = pdst[mi][hf];
            w += __shfl_xor_sync(0xffffffffu, w, 1);
            w += __shfl_xor_sync(0xffffffffu, w, 2);
            pdst[mi][hf] = w;
        }
    __syncthreads();   // protect smem reuse (loop no longer ends with a sync)
    float* sred = (float*)sm;
    if (tig == 0) {
        #pragma unroll
        for (int mi = 0; mi < 2; mi++) {
            int r0 = wM * 32 + mi * 16 + gid;
            sred[(wN * 128 + r0) * 2]         = psrc[mi][0];
            sred[(wN * 128 + r0) * 2 + 1]     = pdst[mi][0];
            sred[(wN * 128 + r0 + 8) * 2]     = psrc[mi][1];
            sred[(wN * 128 + r0 + 8) * 2 + 1] = pdst[mi][1];
        }
    }
    __syncthreads();
    if (tid < 128) {
        int n = m0 + tid;
        if (n < NN) {
            float ss = sred[tid * 2] + sred[(128 + tid) * 2];
            float sd = sred[tid * 2 + 1] + sred[(128 + tid) * 2 + 1];
            g_ssrc[(size_t)n * NBH + b * 4 + hx] = ss;
            g_sdst[(size_t)n * NBH + b * 4 + hx] = sd;
        }
    }
}

// ---------------- fused edge softmax (no max pass) ----------------
__global__ __launch_bounds__(256) void k_sm(const void* ep) {
    __shared__ float wred[8][8];
    int tid = threadIdx.x, wid = tid >> 5, lid = tid & 31;
    int is64 = g_is64;
    int e = blockIdx.x * 256 + tid;
    float pv[8];
    if (e < NE) {
        int sn = esrc(ep, e, is64), dn = edst(ep, e, is64);
        const float* ps = g_ssrc + (size_t)sn * NBH;
        const float* pd = g_sdst + (size_t)dn * NBH;
        #pragma unroll
        for (int i = 0; i < 8; i++) {
            float s = ps[i] + pd[i];
            s = (s > 0.f) ? s : 0.2f * s;
            float p = __expf(s);
            pv[i] = p;
            g_sc[(size_t)e * NBH + i] = p;
        }
    } else {
        #pragma unroll
        for (int i = 0; i < 8; i++) pv[i] = 0.f;
    }
    #pragma unroll
    for (int i = 0; i < 8; i++) {
        float s = pv[i];
        #pragma unroll
        for (int o = 16; o > 0; o >>= 1) s += __shfl_xor_sync(0xffffffffu, s, o);
        if (lid == 0) wred[wid][i] = s;
    }
    __syncthreads();
    if (tid < 8) {
        float s = 0.f;
        #pragma unroll
        for (int w = 0; w < 8; w++) s += wred[w][tid];
        atomicAdd(&g_sum[tid], s);
    }
}

// ---------------- CSR build (parallel deterministic scan) ----------------
__global__ void k_count(const void* ep) {
    int e = blockIdx.x * 256 + threadIdx.x;
    if (e < NE) atomicAdd(&g_cnt[edst(ep, e, g_is64)], 1);
}
__global__ __launch_bounds__(128) void k_bsum() {
    __shared__ int ws[4];
    int tid = threadIdx.x;
    int i = blockIdx.x * 128 + tid;
    int c = (i < NN) ? g_cnt[i] : 0;
    int v = c;
    #pragma unroll
    for (int o = 16; o > 0; o >>= 1) v += __shfl_down_sync(0xffffffffu, v, o);
    if ((tid & 31) == 0) ws[tid >> 5] = v;
    __syncthreads();
    if (tid == 0) g_bsum[blockIdx.x] = ws[0] + ws[1] + ws[2] + ws[3];
}
__global__ __launch_bounds__(256) void k_bscan() {
    __shared__ int s[256];
    int t = threadIdx.x;
    int v = (t < NBLK) ? g_bsum[t] : 0;
    s[t] = v;
    __syncthreads();
    for (int o = 1; o < 256; o <<= 1) {
        int u = (t >= o) ? s[t - o] : 0;
        __syncthreads();
        s[t] += u;
        __syncthreads();
    }
    if (t < NBLK) g_boff[t] = s[t] - v;
    if (t == NBLK - 1) g_off[NN] = s[t];
}
__global__ __launch_bounds__(128) void k_off() {
    __shared__ int ws[4];
    int tid = threadIdx.x, lane = tid & 31, warp = tid >> 5;
    int i = blockIdx.x * 128 + tid;
    int c = (i < NN) ? g_cnt[i] : 0;
    int v = c;
    #pragma unroll
    for (int o = 1; o < 32; o <<= 1) {
        int u = __shfl_up_sync(0xffffffffu, v, o);
        if (lane >= o) v += u;
    }
    if (lane == 31) ws[warp] = v;
    __syncthreads();
    int add = 0;
    #pragma unroll
    for (int w = 0; w < 4; w++) add += (w < warp) ? ws[w] : 0;
    int excl = v - c + add + g_boff[blockIdx.x];
    if (i < NN) { g_off[i] = excl; g_cur[i] = excl; }
}
__global__ void k_fill(const void* ep) {
    int e = blockIdx.x * 256 + threadIdx.x;
    if (e < NE) {
        int pos = atomicAdd(&g_cur[edst(ep, e, g_is64)], 1);
        g_eid[pos] = e;
    }
}

// ---------------- aggregate + layernorm (fp16 gather, half2 lanes) ---------
__global__ __launch_bounds__(128) void k_agg(const void* ep,
                                             const float* __restrict__ gamma,
                                             const float* __restrict__ beta,
                                             float* __restrict__ out) {
    __shared__ float red[8];
    __shared__ int   s_sn[32];
    __shared__ float s_w[32][8];
    int is64 = g_is64;
    int n = blockIdx.x;
    int tid = threadIdx.x;
    int hsel = tid >> 6;
    float2 acc[4] = {};
    int e0 = g_off[n], e1 = g_off[n + 1];
    for (int base = e0; base < e1; base += 32) {
        int cnt = min(32, e1 - base);
        __syncthreads();
        if (tid < cnt) {
            int e = g_eid[base + tid];
            s_sn[tid] = esrc(ep, e, is64);
            *(float4*)&s_w[tid][0] = *(const float4*)(g_sc + (size_t)e * NBH);
            *(float4*)&s_w[tid][4] = *(const float4*)(g_sc + (size_t)e * NBH + 4);
        }
        __syncthreads();
        for (int j = 0; j < cnt; j++) {
            const __half2* trow = (const __half2*)(g_t + (size_t)s_sn[j] * (NB * OF));
            #pragma unroll
            for (int s = 0; s < 4; s++) {
                float2 f = __half22float2(trow[s * 128 + tid]);
                float w = s_w[j][2 * s + hsel];
                acc[s].x += w * f.x;
                acc[s].y += w * f.y;
            }
        }
    }
    __syncthreads();
    #pragma unroll
    for (int s = 0; s < 4; s++) {
        float inv = 1.f / g_sum[2 * s + hsel];
        acc[s].x *= inv;
        acc[s].y *= inv;
    }
    #pragma unroll
    for (int b = 0; b < NB; b++) {
        float2 p0 = acc[2 * b], p1 = acc[2 * b + 1];
        float s1 = p0.x + p0.y + p1.x + p1.y;
        float s2 = p0.x * p0.x + p0.y * p0.y + p1.x * p1.x + p1.y * p1.y;
        #pragma unroll
        for (int o = 16; o > 0; o >>= 1) {
            s1 += __shfl_down_sync(0xffffffffu, s1, o);
            s2 += __shfl_down_sync(0xffffffffu, s2, o);
        }
        if ((tid & 31) == 0) { red[(tid >> 5) * 2] = s1; red[(tid >> 5) * 2 + 1] = s2; }
        __syncthreads();
        float t1 = red[0] + red[2] + red[4] + red[6];
        float t2 = red[1] + red[3] + red[5] + red[7];
        float mu = t1 / (float)OF;
        float var = t2 / (float)OF - mu * mu;
        float rs = rsqrtf(var + LN_EPS);
        float* op = out + ((size_t)b * NN + n) * OF;
        #pragma unroll
        for (int q = 0; q < 2; q++) {
            int s = 2 * b + q;
            int jj = q * 256 + 2 * tid;
            float2 v = acc[s];
            float2 o;
            o.x = (v.x - mu) * rs * gamma[jj] + beta[jj];
            o.y = (v.y - mu) * rs * gamma[jj + 1] + beta[jj + 1];
            *(float2*)(op + jj) = o;
        }
        __syncthreads();
    }
}

extern "C" void kernel_launch(void* const* d_in, const int* in_sizes, int n_in,
                              void* d_out, int out_size) {
    const float* x     = (const float*)d_in[0];
    const void*  ei    = d_in[1];
    const float* W     = (const float*)d_in[2];
    const float* a     = (const float*)d_in[3];
    const float* gamma = (const float*)d_in[4];
    const float* beta  = (const float*)d_in[5];
    float* out = (float*)d_out;

    static cudaStream_t s1 = nullptr;
    static cudaEvent_t ev0 = nullptr, ev1 = nullptr;
    if (!s1) {
        cudaStreamCreateWithFlags(&s1, cudaStreamNonBlocking);
        cudaEventCreateWithFlags(&ev0, cudaEventDisableTiming);
        cudaEventCreateWithFlags(&ev1, cudaEventDisableTiming);
        cudaFuncSetAttribute(k_gemm_mma, cudaFuncAttributeMaxDynamicSharedMemorySize, SMEMB);
    }

    k_convw<<<(NH * KF * DH + 255) / 256, 256>>>(W);

    cudaEventRecord(ev0, 0);
    cudaStreamWaitEvent(s1, ev0, 0);
    k_detect<<<1, 32, 0, s1>>>((const int*)ei);
    k_init<<<(NN + 255) / 256, 256, 0, s1>>>();

    {
        dim3 g(OF / 128, (NN + 127) / 128, NB);
        k_gemm_mma<<<g, 256, SMEMB>>>(x, a);   // 4th launch <- ncu target
    }

    k_count<<<(NE + 255) / 256, 256, 0, s1>>>(ei);
    k_bsum<<<NBLK, 128, 0, s1>>>();
    k_bscan<<<1, 256, 0, s1>>>();
    k_off<<<NBLK, 128, 0, s1>>>();
    k_fill<<<(NE + 255) / 256, 256, 0, s1>>>(ei);
    cudaEventRecord(ev1, s1);

    cudaStreamWaitEvent(0, ev1, 0);
    k_sm<<<(NE + 255) / 256, 256>>>(ei);
    k_agg<<<NN, 128>>>(ei, gamma, beta, out);
}

// round 16
// speedup vs baseline: 1.3907x; 1.2407x over previous
#include <cuda_runtime.h>
#include <cuda_fp16.h>
#include <cstdint>

#define NB 2
#define NN 30000
#define NE 120000
#define KF 512
#define NH 4
#define DH 128
#define OF 512
#define NBH 8
#define NBLK 235
#define LN_EPS 1e-5f

__device__ __half g_t[(size_t)NN * NB * OF];   // [n][b][512] fp16
__device__ __half g_wthi[OF * KF];             // [col][k], col = h*128+d
__device__ float  g_ssrc[(size_t)NN * NBH];    // [n][b*4+h]
__device__ float  g_sdst[(size_t)NN * NBH];
__device__ float  g_sc[(size_t)NE * NBH];      // [e][b*4+h]
__device__ float  g_sum[NBH];
__device__ int    g_cnt[NN];
__device__ int    g_bsum[NBLK];
__device__ int    g_boff[NBLK];
__device__ int    g_off[NN + 1];
__device__ int    g_cur[NN];
__device__ int    g_eid[NE];
__device__ int    g_is64;

__device__ __forceinline__ int esrc(const void* ep, int e, int is64) {
    return is64 ? (int)((const long long*)ep)[e] : ((const int*)ep)[e];
}
__device__ __forceinline__ int edst(const void* ep, int e, int is64) {
    return is64 ? (int)((const long long*)ep)[NE + e] : ((const int*)ep)[NE + e];
}
__device__ __forceinline__ uint32_t smem_u32(const void* p) {
    uint32_t a;
    asm("{ .reg .u64 t; cvta.to.shared.u64 t, %1; cvt.u32.u64 %0, t; }" : "=r"(a) : "l"(p));
    return a;
}
__device__ __forceinline__ void cpa16(uint32_t dst, const void* src) {
    asm volatile("cp.async.ca.shared.global [%0], [%1], 16;"
                 :: "r"(dst), "l"(src) : "memory");
}
__device__ __forceinline__ void ldsm_x4(uint32_t addr, uint32_t& r0, uint32_t& r1,
                                        uint32_t& r2, uint32_t& r3) {
    asm volatile("ldmatrix.sync.aligned.m8n8.x4.shared.b16 {%0,%1,%2,%3}, [%4];"
                 : "=r"(r0), "=r"(r1), "=r"(r2), "=r"(r3) : "r"(addr));
}

// ---------------- prep kernels ----------------
__global__ void k_detect(const int* ei32) {
    if (threadIdx.x == 0) {
        int ok = 1;
        for (int j = 0; j < 64; j++)
            if (ei32[2 * j + 1] != 0) ok = 0;
        g_is64 = ok;
    }
}
__global__ void k_init() {
    int i = blockIdx.x * blockDim.x + threadIdx.x;
    if (i < NN) g_cnt[i] = 0;
    if (i < NBH) g_sum[i] = 0.f;
}
__global__ void k_convw(const float* __restrict__ W) {
    int i = blockIdx.x * blockDim.x + threadIdx.x;  // h,k,d
    if (i >= NH * KF * DH) return;
    int h = i / (KF * DH), r = i % (KF * DH), k = r / DH, d = r % DH;
    int n = h * DH + d;
    g_wthi[(size_t)n * KF + k] = __float2half_rn(W[i]);
}

// ---- mma.sync GEMM: 128x128/CTA, K=512, single-term fp16, double buffer ----
// SMEM per buffer: A[0..10239], B[10240..20479]; buffers at 0 / 20480.
#define PITCHB 80
#define TERMB  10240
#define BUFB   20480
#define SMEMB  40960

__device__ __forceinline__ void ldgA(float4* ar, const float* __restrict__ xb,
                                     int m0, int kc, int tid) {
    #pragma unroll
    for (int j = 0; j < 4; j++) {
        int idx = j * 256 + tid;
        int row = idx >> 3, c4 = idx & 7;
        int gr = m0 + row;
        ar[j] = (gr < NN) ? *(const float4*)(xb + (size_t)gr * KF + kc * 32 + c4 * 4)
                          : make_float4(0.f, 0.f, 0.f, 0.f);
    }
}
__device__ __forceinline__ void stsA(const float4* ar, char* sm, int buf, int tid) {
    char* base = sm + buf * BUFB;
    #pragma unroll
    for (int j = 0; j < 4; j++) {
        int idx = j * 256 + tid;
        int row = idx >> 3, c4 = idx & 7;
        float4 v = ar[j];
        __half h0 = __float2half_rn(v.x), h1 = __float2half_rn(v.y);
        __half h2 = __float2half_rn(v.z), h3 = __float2half_rn(v.w);
        uint32_t hi0 = (uint32_t)__half_as_ushort(h0) |
                       ((uint32_t)__half_as_ushort(h1) << 16);
        uint32_t hi1 = (uint32_t)__half_as_ushort(h2) |
                       ((uint32_t)__half_as_ushort(h3) << 16);
        *(uint2*)(base + row * PITCHB + c4 * 8) = make_uint2(hi0, hi1);
    }
}
__device__ __forceinline__ void loadB(uint32_t sb, int buf, int kc, int bn, int tid) {
    #pragma unroll
    for (int i = 0; i < 2; i++) {
        int idx = i * 256 + tid;
        int row = idx >> 2, seg = idx & 3;
        uint32_t dst = sb + buf * BUFB + TERMB + row * PITCHB + seg * 16;
        const __half* src = g_wthi + (size_t)(bn + row) * KF + kc * 32 + seg * 8;
        cpa16(dst, src);
    }
    asm volatile("cp.async.commit_group;" ::: "memory");
}

#define MMA_F16(c, a0, a1, a2, a3, b0, b1) \
    asm volatile( \
        "mma.sync.aligned.m16n8k16.row.col.f32.f16.f16.f32 " \
        "{%0,%1,%2,%3}, {%4,%5,%6,%7}, {%8,%9}, {%0,%1,%2,%3};" \
        : "+f"((c)[0]), "+f"((c)[1]), "+f"((c)[2]), "+f"((c)[3]) \
        : "r"(a0), "r"(a1), "r"(a2), "r"(a3), "r"(b0), "r"(b1))

__global__ __launch_bounds__(256, 2) void k_gemm_mma(const float* __restrict__ x,
                                                     const float* __restrict__ ga) {
    extern __shared__ float4 smf4[];
    char* sm = (char*)smf4;
    uint32_t sb = smem_u32(sm);
    int tid = threadIdx.x, lid = tid & 31, wid = tid >> 5;
    int gid = lid >> 2, tig = lid & 3;
    int wM = wid & 3, wN = wid >> 2;
    int hx = blockIdx.x;
    int m0 = blockIdx.y * 128, bn = hx * 128;
    int b = blockIdx.z;
    const float* xb = x + (size_t)b * NN * KF;

    uint32_t aoff = (uint32_t)((lid & 15) * PITCHB + (((lid >> 4) << 3)) * 2);
    uint32_t boff = (uint32_t)((((lid & 7) + ((lid >> 4) << 3))) * PITCHB +
                               ((((lid >> 3) & 1) << 3)) * 2);

    float acc[2][8][4];
    #pragma unroll
    for (int mi = 0; mi < 2; mi++)
        #pragma unroll
        for (int ni = 0; ni < 8; ni++)
            #pragma unroll
            for (int q = 0; q < 4; q++) acc[mi][ni][q] = 0.f;

    float4 ar[4];
    ldgA(ar, xb, m0, 0, tid);
    stsA(ar, sm, 0, tid);
    loadB(sb, 0, 0, bn, tid);
    ldgA(ar, xb, m0, 1, tid);

    for (int kc = 0; kc < 16; kc++) {
        if (kc < 15) {
            stsA(ar, sm, (kc + 1) & 1, tid);
            loadB(sb, (kc + 1) & 1, kc + 1, bn, tid);
            if (kc < 14) ldgA(ar, xb, m0, kc + 2, tid);
            asm volatile("cp.async.wait_group 1;" ::: "memory");
        } else {
            asm volatile("cp.async.wait_group 0;" ::: "memory");
        }
        __syncthreads();
        uint32_t sA = sb + (kc & 1) * BUFB;
        uint32_t sB = sA + TERMB;
        #pragma unroll
        for (int s = 0; s < 2; s++) {
            uint32_t Abase = sA + wM * 32 * PITCHB + aoff + s * 32;
            uint32_t Bbase = sB + wN * 64 * PITCHB + boff + s * 32;
            uint32_t ah[2][4];
            ldsm_x4(Abase,               ah[0][0], ah[0][1], ah[0][2], ah[0][3]);
            ldsm_x4(Abase + 16 * PITCHB, ah[1][0], ah[1][1], ah[1][2], ah[1][3]);
            uint32_t bh_[8][2];
            #pragma unroll
            for (int j = 0; j < 4; j++)
                ldsm_x4(Bbase + j * 16 * PITCHB,
                        bh_[2 * j][0], bh_[2 * j][1], bh_[2 * j + 1][0], bh_[2 * j + 1][1]);
            #pragma unroll
            for (int ni = 0; ni < 8; ni++) {
                MMA_F16(acc[0][ni], ah[0][0], ah[0][1], ah[0][2], ah[0][3], bh_[ni][0], bh_[ni][1]);
                MMA_F16(acc[1][ni], ah[1][0], ah[1][1], ah[1][2], ah[1][3], bh_[ni][0], bh_[ni][1]);
            }
        }
        __syncthreads();
    }

    // epilogue: write g_t[n][b][512] (fp16) + fused s_src/s_dst dots for head hx
    float psrc[2][2] = {{0.f, 0.f}, {0.f, 0.f}};
    float pdst[2][2] = {{0.f, 0.f}, {0.f, 0.f}};
    #pragma unroll
    for (int mi = 0; mi < 2; mi++) {
        #pragma unroll
        for (int ni = 0; ni < 8; ni++) {
            int row = m0 + wM * 32 + mi * 16 + gid;
            int d0 = wN * 64 + ni * 8 + tig * 2;
            float c0 = acc[mi][ni][0], c1 = acc[mi][ni][1];
            float c2 = acc[mi][ni][2], c3 = acc[mi][ni][3];
            float a0 = __ldg(ga + hx * 256 + d0);
            float a1 = __ldg(ga + hx * 256 + d0 + 1);
            float e0 = __ldg(ga + hx * 256 + 128 + d0);
            float e1 = __ldg(ga + hx * 256 + 128 + d0 + 1);
            psrc[mi][0] += c0 * a0 + c1 * a1;
            psrc[mi][1] += c2 * a0 + c3 * a1;
            pdst[mi][0] += c0 * e0 + c1 * e1;
            pdst[mi][1] += c2 * e0 + c3 * e1;
            __half* base = g_t + ((size_t)row * NB + b) * OF + hx * 128 + d0;
            if (row < NN) *(__half2*)base = __floats2half2_rn(c0, c1);
            if (row + 8 < NN)
                *(__half2*)(base + 8 * (size_t)(NB * OF)) = __floats2half2_rn(c2, c3);
        }
    }
    #pragma unroll
    for (int mi = 0; mi < 2; mi++)
        #pragma unroll
        for (int hf = 0; hf < 2; hf++) {
            float v = psrc[mi][hf];
            v += __shfl_xor_sync(0xffffffffu, v, 1);
            v += __shfl_xor_sync(0xffffffffu, v, 2);
            psrc[mi][hf] = v;
            float w = pdst[mi][hf];
            w += __shfl_xor_sync(0xffffffffu, w, 1);
            w += __shfl_xor_sync(0xffffffffu, w, 2);
            pdst[mi][hf] = w;
        }
    float* sred = (float*)sm;
    if (tig == 0) {
        #pragma unroll
        for (int mi = 0; mi < 2; mi++) {
            int r0 = wM * 32 + mi * 16 + gid;
            sred[(wN * 128 + r0) * 2]         = psrc[mi][0];
            sred[(wN * 128 + r0) * 2 + 1]     = pdst[mi][0];
            sred[(wN * 128 + r0 + 8) * 2]     = psrc[mi][1];
            sred[(wN * 128 + r0 + 8) * 2 + 1] = pdst[mi][1];
        }
    }
    __syncthreads();
    if (tid < 128) {
        int n = m0 + tid;
        if (n < NN) {
            float ss = sred[tid * 2] + sred[(128 + tid) * 2];
            float sd = sred[tid * 2 + 1] + sred[(128 + tid) * 2 + 1];
            g_ssrc[(size_t)n * NBH + b * 4 + hx] = ss;
            g_sdst[(size_t)n * NBH + b * 4 + hx] = sd;
        }
    }
}

// ---------------- fused edge softmax (no max pass) ----------------
__global__ __launch_bounds__(256) void k_sm(const void* ep) {
    __shared__ float wred[8][8];
    int tid = threadIdx.x, wid = tid >> 5, lid = tid & 31;
    int is64 = g_is64;
    int e = blockIdx.x * 256 + tid;
    float pv[8];
    if (e < NE) {
        int sn = esrc(ep, e, is64), dn = edst(ep, e, is64);
        const float* ps = g_ssrc + (size_t)sn * NBH;
        const float* pd = g_sdst + (size_t)dn * NBH;
        #pragma unroll
        for (int i = 0; i < 8; i++) {
            float s = ps[i] + pd[i];
            s = (s > 0.f) ? s : 0.2f * s;
            float p = __expf(s);
            pv[i] = p;
            g_sc[(size_t)e * NBH + i] = p;
        }
    } else {
        #pragma unroll
        for (int i = 0; i < 8; i++) pv[i] = 0.f;
    }
    #pragma unroll
    for (int i = 0; i < 8; i++) {
        float s = pv[i];
        #pragma unroll
        for (int o = 16; o > 0; o >>= 1) s += __shfl_xor_sync(0xffffffffu, s, o);
        if (lid == 0) wred[wid][i] = s;
    }
    __syncthreads();
    if (tid < 8) {
        float s = 0.f;
        #pragma unroll
        for (int w = 0; w < 8; w++) s += wred[w][tid];
        atomicAdd(&g_sum[tid], s);
    }
}

// ---------------- CSR build (parallel deterministic scan) ----------------
__global__ void k_count(const void* ep) {
    int e = blockIdx.x * 256 + threadIdx.x;
    if (e < NE) atomicAdd(&g_cnt[edst(ep, e, g_is64)], 1);
}
__global__ __launch_bounds__(128) void k_bsum() {
    __shared__ int ws[4];
    int tid = threadIdx.x;
    int i = blockIdx.x * 128 + tid;
    int c = (i < NN) ? g_cnt[i] : 0;
    int v = c;
    #pragma unroll
    for (int o = 16; o > 0; o >>= 1) v += __shfl_down_sync(0xffffffffu, v, o);
    if ((tid & 31) == 0) ws[tid >> 5] = v;
    __syncthreads();
    if (tid == 0) g_bsum[blockIdx.x] = ws[0] + ws[1] + ws[2] + ws[3];
}
__global__ __launch_bounds__(256) void k_bscan() {
    __shared__ int s[256];
    int t = threadIdx.x;
    int v = (t < NBLK) ? g_bsum[t] : 0;
    s[t] = v;
    __syncthreads();
    for (int o = 1; o < 256; o <<= 1) {
        int u = (t >= o) ? s[t - o] : 0;
        __syncthreads();
        s[t] += u;
        __syncthreads();
    }
    if (t < NBLK) g_boff[t] = s[t] - v;
    if (t == NBLK - 1) g_off[NN] = s[t];
}
__global__ __launch_bounds__(128) void k_off() {
    __shared__ int ws[4];
    int tid = threadIdx.x, lane = tid & 31, warp = tid >> 5;
    int i = blockIdx.x * 128 + tid;
    int c = (i < NN) ? g_cnt[i] : 0;
    int v = c;
    #pragma unroll
    for (int o = 1; o < 32; o <<= 1) {
        int u = __shfl_up_sync(0xffffffffu, v, o);
        if (lane >= o) v += u;
    }
    if (lane == 31) ws[warp] = v;
    __syncthreads();
    int add = 0;
    #pragma unroll
    for (int w = 0; w < 4; w++) add += (w < warp) ? ws[w] : 0;
    int excl = v - c + add + g_boff[blockIdx.x];
    if (i < NN) { g_off[i] = excl; g_cur[i] = excl; }
}
__global__ void k_fill(const void* ep) {
    int e = blockIdx.x * 256 + threadIdx.x;
    if (e < NE) {
        int pos = atomicAdd(&g_cur[edst(ep, e, g_is64)], 1);
        g_eid[pos] = e;
    }
}

// ---------------- aggregate + layernorm (fp16 gather, half2 lanes) ---------
__global__ __launch_bounds__(128) void k_agg(const void* ep,
                                             const float* __restrict__ gamma,
                                             const float* __restrict__ beta,
                                             float* __restrict__ out) {
    __shared__ float red[8];
    __shared__ int   s_sn[32];
    __shared__ float s_w[32][8];
    int is64 = g_is64;
    int n = blockIdx.x;
    int tid = threadIdx.x;
    int hsel = tid >> 6;
    float2 acc[4] = {};
    int e0 = g_off[n], e1 = g_off[n + 1];
    for (int base = e0; base < e1; base += 32) {
        int cnt = min(32, e1 - base);
        __syncthreads();
        if (tid < cnt) {
            int e = g_eid[base + tid];
            s_sn[tid] = esrc(ep, e, is64);
            *(float4*)&s_w[tid][0] = *(const float4*)(g_sc + (size_t)e * NBH);
            *(float4*)&s_w[tid][4] = *(const float4*)(g_sc + (size_t)e * NBH + 4);
        }
        __syncthreads();
        for (int j = 0; j < cnt; j++) {
            const __half2* trow = (const __half2*)(g_t + (size_t)s_sn[j] * (NB * OF));
            #pragma unroll
            for (int s = 0; s < 4; s++) {
                float2 f = __half22float2(trow[s * 128 + tid]);
                float w = s_w[j][2 * s + hsel];
                acc[s].x += w * f.x;
                acc[s].y += w * f.y;
            }
        }
    }
    __syncthreads();
    #pragma unroll
    for (int s = 0; s < 4; s++) {
        float inv = 1.f / g_sum[2 * s + hsel];
        acc[s].x *= inv;
        acc[s].y *= inv;
    }
    #pragma unroll
    for (int b = 0; b < NB; b++) {
        float2 p0 = acc[2 * b], p1 = acc[2 * b + 1];
        float s1 = p0.x + p0.y + p1.x + p1.y;
        float s2 = p0.x * p0.x + p0.y * p0.y + p1.x * p1.x + p1.y * p1.y;
        #pragma unroll
        for (int o = 16; o > 0; o >>= 1) {
            s1 += __shfl_down_sync(0xffffffffu, s1, o);
            s2 += __shfl_down_sync(0xffffffffu, s2, o);
        }
        if ((tid & 31) == 0) { red[(tid >> 5) * 2] = s1; red[(tid >> 5) * 2 + 1] = s2; }
        __syncthreads();
        float t1 = red[0] + red[2] + red[4] + red[6];
        float t2 = red[1] + red[3] + red[5] + red[7];
        float mu = t1 / (float)OF;
        float var = t2 / (float)OF - mu * mu;
        float rs = rsqrtf(var + LN_EPS);
        float* op = out + ((size_t)b * NN + n) * OF;
        #pragma unroll
        for (int q = 0; q < 2; q++) {
            int s = 2 * b + q;
            int jj = q * 256 + 2 * tid;
            float2 v = acc[s];
            float2 o;
            o.x = (v.x - mu) * rs * gamma[jj] + beta[jj];
            o.y = (v.y - mu) * rs * gamma[jj + 1] + beta[jj + 1];
            *(float2*)(op + jj) = o;
        }
        __syncthreads();
    }
}

extern "C" void kernel_launch(void* const* d_in, const int* in_sizes, int n_in,
                              void* d_out, int out_size) {
    const float* x     = (const float*)d_in[0];
    const void*  ei    = d_in[1];
    const float* W     = (const float*)d_in[2];
    const float* a     = (const float*)d_in[3];
    const float* gamma = (const float*)d_in[4];
    const float* beta  = (const float*)d_in[5];
    float* out = (float*)d_out;

    static cudaStream_t s1 = nullptr;
    static cudaEvent_t ev0 = nullptr, ev1 = nullptr;
    if (!s1) {
        cudaStreamCreateWithFlags(&s1, cudaStreamNonBlocking);
        cudaEventCreateWithFlags(&ev0, cudaEventDisableTiming);
        cudaEventCreateWithFlags(&ev1, cudaEventDisableTiming);
        cudaFuncSetAttribute(k_gemm_mma, cudaFuncAttributeMaxDynamicSharedMemorySize, SMEMB);
    }

    k_convw<<<(NH * KF * DH + 255) / 256, 256>>>(W);

    cudaEventRecord(ev0, 0);
    cudaStreamWaitEvent(s1, ev0, 0);
    k_detect<<<1, 32, 0, s1>>>((const int*)ei);
    k_init<<<(NN + 255) / 256, 256, 0, s1>>>();

    {
        dim3 g(OF / 128, (NN + 127) / 128, NB);
        k_gemm_mma<<<g, 256, SMEMB>>>(x, a);   // 4th launch <- ncu target
    }

    k_count<<<(NE + 255) / 256, 256, 0, s1>>>(ei);
    k_bsum<<<NBLK, 128, 0, s1>>>();
    k_bscan<<<1, 256, 0, s1>>>();
    k_off<<<NBLK, 128, 0, s1>>>();
    k_fill<<<(NE + 255) / 256, 256, 0, s1>>>(ei);
    cudaEventRecord(ev1, s1);

    cudaStreamWaitEvent(0, ev1, 0);
    k_sm<<<(NE + 255) / 256, 256>>>(ei);
    k_agg<<<NN, 128>>>(ei, gamma, beta, out);
}